// round 14
// baseline (speedup 1.0000x reference)
#include <cuda_runtime.h>
#include <cuda_fp16.h>
#include <math.h>
#include <cstdint>

#define HW 128
#define NPIX (HW*HW)          // 16384
#define TOPK 300
#define NLINES 20000
#define DIM_LOI 128
#define NPTS0 32
#define NPTS1 8
#define DIM_FC 1024
#define NLAB 3

// row split for pipelined halves (multiple of 128 and of 2)
#define M_SPLIT 9984

// pair-permutation within a 32-k block (16 pairs): p' = (p&3)*4 + (p>>2)
__host__ __device__ __forceinline__ int khperm(int k) {
    int p = k >> 1;
    int pp = ((p & 3) << 2) | (p >> 2);
    return (pp << 1) | (k & 1);
}

// ---------------- scratch (device globals; no allocation allowed) ----------
__device__ __align__(16) __half g_loiTh[NPIX * DIM_LOI];   // [hw][c] fp16 4 MB
__device__ __align__(16) float  g_juncs[TOPK * 2];
__device__ __align__(16) __half g_feats[NLINES * DIM_FC];  // permuted fp16
__device__ __align__(16) __half g_h1[NLINES * DIM_FC];     // permuted fp16
__device__ __align__(16) __half g_w1T[DIM_FC * DIM_FC];    // W1^T [N][kperm]
__device__ __align__(16) __half g_w2T[DIM_FC * DIM_FC];    // W2^T [N][kperm]
__device__ __align__(16) float  g_part[8 * NLINES * NLAB]; // fused-out partials

// ======================= PTX helpers ========================================
__device__ __forceinline__ uint32_t smem_u32(const void* p) {
    uint32_t a;
    asm("{ .reg .u64 t; cvta.to.shared.u64 t, %1; cvt.u32.u64 %0, t; }" : "=r"(a) : "l"(p));
    return a;
}
#define CP_ASYNC16(sm, g) \
    asm volatile("cp.async.cg.shared.global [%0], [%1], 16;" :: "r"(sm), "l"(g) : "memory")
#define CP_COMMIT() asm volatile("cp.async.commit_group;" ::: "memory")
#define CP_WAIT(n)  asm volatile("cp.async.wait_group %0;" :: "n"(n) : "memory")

__device__ __forceinline__ void mma_f16(float* c,
                                        uint32_t a0, uint32_t a1, uint32_t a2, uint32_t a3,
                                        uint32_t b0, uint32_t b1) {
    asm volatile(
        "mma.sync.aligned.m16n8k16.row.col.f32.f16.f16.f32 "
        "{%0,%1,%2,%3}, {%4,%5,%6,%7}, {%8,%9}, {%0,%1,%2,%3};"
        : "+f"(c[0]), "+f"(c[1]), "+f"(c[2]), "+f"(c[3])
        : "r"(a0), "r"(a1), "r"(a2), "r"(a3), "r"(b0), "r"(b1));
}

// ---------------- kernel 1: NMS + compact + small bitonic top-k ------------
#define SORTN 4096
__global__ void topk_juncs_kernel(const float* __restrict__ jloc,
                                  const float* __restrict__ joff) {
    __shared__ unsigned long long keys[SORTN];
    __shared__ int cnt;
    int tid = threadIdx.x;
    if (tid == 0) cnt = 0;
    #pragma unroll
    for (int i = tid; i < SORTN; i += 1024) keys[i] = 0ull;
    __syncthreads();

    for (int i = tid; i < NPIX; i += 1024) {
        int y = i >> 7, x = i & 127;
        float v = jloc[i];
        float m = v;
        #pragma unroll
        for (int dy = -1; dy <= 1; dy++)
            #pragma unroll
            for (int dx = -1; dx <= 1; dx++) {
                int yy = y + dy, xx = x + dx;
                if (yy >= 0 && yy < HW && xx >= 0 && xx < HW)
                    m = fmaxf(m, jloc[yy * HW + xx]);
            }
        if (v == m && v > 0.0f) {
            int p = atomicAdd(&cnt, 1);
            if (p < SORTN)
                keys[p] = ((unsigned long long)__float_as_uint(v) << 32)
                        | (unsigned long long)(0xFFFFFFFFu - (unsigned)i);
        }
    }
    __syncthreads();

    for (int k = 2; k <= SORTN; k <<= 1) {
        for (int j = k >> 1; j > 0; j >>= 1) {
            #pragma unroll
            for (int i = tid; i < SORTN; i += 1024) {
                int ixj = i ^ j;
                if (ixj > i) {
                    unsigned long long a = keys[i], b = keys[ixj];
                    bool up = ((i & k) == 0);
                    if ((a < b) == up) { keys[i] = b; keys[ixj] = a; }
                }
            }
            __syncthreads();
        }
    }

    if (tid < TOPK) {
        unsigned long long key = keys[tid];
        unsigned idx = 0xFFFFFFFFu - (unsigned)(key & 0xFFFFFFFFull);
        float j0 = joff[idx];
        float j1 = joff[NPIX + idx];
        float sx = 1.0f / (1.0f + expf(-j0));
        float sy = 1.0f / (1.0f + expf(-j1));
        g_juncs[2 * tid + 0] = (float)(idx & 127) + sx;
        g_juncs[2 * tid + 1] = (float)(idx >> 7) + sy;
    }
}

// ---------------- kernel 2a: transpose loi [C][HW*HW] -> [HW*HW][C] fp16 ---
__global__ void transpose_loi_kernel(const float* __restrict__ in) {
    __shared__ float tile[32][33];
    int p0 = blockIdx.x * 32;
    int c0 = blockIdx.y * 32;
    int tx = threadIdx.x, ty = threadIdx.y;   // 32 x 8
    #pragma unroll
    for (int i = 0; i < 32; i += 8)
        tile[ty + i][tx] = in[(size_t)(c0 + ty + i) * NPIX + p0 + tx];
    __syncthreads();
    #pragma unroll
    for (int i = 0; i < 32; i += 8)
        g_loiTh[(size_t)(p0 + ty + i) * DIM_LOI + c0 + tx] =
            __float2half_rn(tile[tx][ty + i]);
}

// ---------------- kernel 2b: both W -> W^T with k-perm + fp16 (z = which) --
__global__ void transposeW_kernel(const float* __restrict__ W1,
                                  const float* __restrict__ W2) {
    __shared__ float tile[32][33];
    const float* in = blockIdx.z ? W2 : W1;
    __half* out = blockIdx.z ? g_w2T : g_w1T;
    int p0 = blockIdx.x * 32;   // n block
    int c0 = blockIdx.y * 32;   // k block
    int tx = threadIdx.x, ty = threadIdx.y;   // 32 x 8
    #pragma unroll
    for (int i = 0; i < 32; i += 8)
        tile[ty + i][tx] = in[(size_t)(c0 + ty + i) * DIM_FC + p0 + tx];
    __syncthreads();
    #pragma unroll
    for (int i = 0; i < 32; i += 8)
        out[(size_t)(p0 + ty + i) * DIM_FC + c0 + khperm(tx)] =
            __float2half_rn(tile[tx][ty + i]);
}

// ---------------- kernel 3: line sampling + bilinear + group max -----------
// 256 threads, 2 lines per block starting at n0base.
__global__ void sample_kernel(const int* __restrict__ edge, int n0base) {
    __shared__ int   s_off[2][NPTS0][4];
    __shared__ float s_w[2][NPTS0][4];
    __shared__ __align__(16) float s_out[2][8][136];

    int n0 = n0base + blockIdx.x * 2;
    int tid = threadIdx.x;
    int li  = tid >> 7;          // which line (0/1)
    int t128 = tid & 127;
    int pg = t128 >> 4;          // maxpool group 0..7
    int cq = t128 & 15;          // 8-channel chunk (16 B fp16)

    if (tid < 64) {
        int l = tid >> 5;        // line
        int pt = tid & 31;       // point
        int n = n0 + l;
        int e0 = edge[2 * n + 0];
        int e1 = edge[2 * n + 1];
        float Ux = g_juncs[2 * e0 + 0], Uy = g_juncs[2 * e0 + 1];
        float Vx = g_juncs[2 * e1 + 0], Vy = g_juncs[2 * e1 + 1];
        float t = (float)pt * (1.0f / 31.0f);
        float px = Ux * t + Vx * (1.0f - t) - 0.5f;
        float py = Uy * t + Vy * (1.0f - t) - 0.5f;
        float x0 = fminf(fmaxf(floorf(px), 0.0f), 127.0f);
        float y0 = fminf(fmaxf(floorf(py), 0.0f), 127.0f);
        float x1 = fminf(x0 + 1.0f, 127.0f);
        float y1 = fminf(y0 + 1.0f, 127.0f);
        int ix0 = (int)x0, iy0 = (int)y0, ix1 = (int)x1, iy1 = (int)y1;
        s_off[l][pt][0] = (iy0 * HW + ix0) * DIM_LOI;
        s_off[l][pt][1] = (iy1 * HW + ix0) * DIM_LOI;
        s_off[l][pt][2] = (iy0 * HW + ix1) * DIM_LOI;
        s_off[l][pt][3] = (iy1 * HW + ix1) * DIM_LOI;
        s_w[l][pt][0] = (y1 - py) * (x1 - px);
        s_w[l][pt][1] = (py - y0) * (x1 - px);
        s_w[l][pt][2] = (y1 - py) * (px - x0);
        s_w[l][pt][3] = (py - y0) * (px - x0);
    }
    __syncthreads();

    float m[8];
    #pragma unroll
    for (int i = 0; i < 8; i++) m[i] = -1e30f;

    #pragma unroll
    for (int k = 0; k < 4; k++) {
        int p = pg * 4 + k;
        float w0 = s_w[li][p][0], w1 = s_w[li][p][1];
        float w2 = s_w[li][p][2], w3 = s_w[li][p][3];
        uint4 u0 = *(const uint4*)(g_loiTh + s_off[li][p][0] + cq * 8);
        uint4 u1 = *(const uint4*)(g_loiTh + s_off[li][p][1] + cq * 8);
        uint4 u2 = *(const uint4*)(g_loiTh + s_off[li][p][2] + cq * 8);
        uint4 u3 = *(const uint4*)(g_loiTh + s_off[li][p][3] + cq * 8);
        const __half2* h0 = (const __half2*)&u0;
        const __half2* h1 = (const __half2*)&u1;
        const __half2* h2 = (const __half2*)&u2;
        const __half2* h3 = (const __half2*)&u3;
        #pragma unroll
        for (int j = 0; j < 4; j++) {
            float2 a = __half22float2(h0[j]);
            float2 b = __half22float2(h1[j]);
            float2 c = __half22float2(h2[j]);
            float2 d = __half22float2(h3[j]);
            float vx = w0 * a.x + w1 * b.x + w2 * c.x + w3 * d.x;
            float vy = w0 * a.y + w1 * b.y + w2 * c.y + w3 * d.y;
            m[2 * j + 0] = fmaxf(m[2 * j + 0], vx);
            m[2 * j + 1] = fmaxf(m[2 * j + 1], vy);
        }
    }

    // conflict-free staging: 16-lane group writes 256 contiguous bytes
    {
        float4* dst = (float4*)&s_out[li][pg][cq * 8];
        dst[0] = make_float4(m[0], m[1], m[2], m[3]);
        dst[1] = make_float4(m[4], m[5], m[6], m[7]);
    }
    __syncthreads();

    // emit permuted fp16 feats: feature f = ch*8 + pg  ->  s_out[li][f&7][f>>3]
    {
        size_t base = (size_t)(n0 + li) * DIM_FC;
        #pragma unroll
        for (int r = 0; r < 8; r++) {
            int f = t128 + 128 * r;
            float v = s_out[li][f & 7][f >> 3];
            int pos = (f & ~31) | khperm(f & 31);
            g_feats[base + pos] = __float2half_rn(v);
        }
    }
}

// ---------------- kernel 4: fp16 mma GEMM, 128x128 tile, 64x32 warp tile ---
// BK=64, 3-stage cp.async ring, one __syncthreads per k-tile, XOR swizzle.
// Row offset m0 lets halves of the row space run as separate launches.
// MODE 0: C = relu(A@BT^T + bias), fp16 k-permuted out
// MODE 1: fused final: partial[bx][row][lab] = sum_cols relu(acc+bias)*W3[col][lab]
#define BK 64                          // halves per k-tile (128 B per row)
#define NKT (DIM_FC / BK)              // 16
#define BM 128
#define BN 128
#define ATILE (BM * BK)                // 8192 halves
#define BTILE (BN * BK)
#define STAGE (ATILE + BTILE)          // 16384 halves = 32 KB
#define NSTG 3

template <int MODE>
__global__ __launch_bounds__(256, 2)
void hgemm_kernel(const __half* __restrict__ A, const __half* __restrict__ BT,
                  const float* __restrict__ bias, const float* __restrict__ W3,
                  void* __restrict__ Cout, int M, int m0)
{
    extern __shared__ __half smem[];   // [NSTG][A | B]
    __shared__ float sbias[BN];
    __shared__ float sW3[BN * NLAB];
    __shared__ float sP[4][BM][NLAB];
    const uint32_t sbase = smem_u32(smem);
    const int tid = threadIdx.x;
    const int lane = tid & 31;
    const int warp = tid >> 5;
    const int wm = warp & 1;           // 2 row slabs of 64
    const int wn = warp >> 1;          // 4 col slabs of 32
    const int bn = blockIdx.x * BN;
    const int bm = m0 + blockIdx.y * BM;

    if (tid < BN) sbias[tid] = bias[bn + tid];
    if (MODE == 1) {
        #pragma unroll
        for (int i = tid; i < BN * NLAB; i += 256) sW3[i] = W3[bn * NLAB + i];
    }

    // global->smem: 128 B per row -> 8 threads/row (16 B chunks, xor-swizzled)
    const int lrow = tid >> 3;         // 0..31
    const int lchk = tid & 7;          // 16B chunk index
    const int schk = lchk ^ ((lrow & 1) << 2);   // swizzled chunk

    const __half* gA[4];
    uint32_t sA[4];
    const __half* gB[4];
    uint32_t sB[4];
    #pragma unroll
    for (int i = 0; i < 4; i++) {
        int row = lrow + 32 * i;       // parity(row) == parity(lrow)
        int ar = bm + row; if (ar >= M) ar = M - 1;
        gA[i] = A + (size_t)ar * DIM_FC + lchk * 8;
        sA[i] = sbase + (row * BK + schk * 8) * 2;
        gB[i] = BT + (size_t)(bn + row) * DIM_FC + lchk * 8;
        sB[i] = sbase + (ATILE + row * BK + schk * 8) * 2;
    }

    float acc[4][4][4];
    #pragma unroll
    for (int mf = 0; mf < 4; mf++)
        #pragma unroll
        for (int nf = 0; nf < 4; nf++)
            #pragma unroll
            for (int qq = 0; qq < 4; qq++) acc[mf][nf][qq] = 0.0f;

    // prologue: ktile 0 -> stage 0
    #pragma unroll
    for (int i = 0; i < 4; i++) {
        CP_ASYNC16(sA[i], gA[i]);
        CP_ASYNC16(sB[i], gB[i]);
    }
    CP_COMMIT();

    const int g  = lane >> 2;
    const int c0 = lane & 3;
    const int gx = (g & 1) << 2;       // frag chunk xor (row parity = g&1)

    int cs = 0;                        // current stage
    int ns = 1;                        // next stage
    for (int kt = 0; kt < NKT; kt++) {
        if (kt + 1 < NKT) {
            uint32_t soff = (uint32_t)ns * (STAGE * 2);
            int goff = (kt + 1) * BK;
            #pragma unroll
            for (int i = 0; i < 4; i++) {
                CP_ASYNC16(sA[i] + soff, gA[i] + goff);
                CP_ASYNC16(sB[i] + soff, gB[i] + goff);
            }
            CP_COMMIT();
            CP_WAIT(1);
        } else {
            CP_WAIT(0);
        }
        __syncthreads();

        const __half* As = smem + cs * STAGE;
        const __half* Bs = As + ATILE;

        #pragma unroll
        for (int h = 0; h < 2; h++) {  // two 32-k half-blocks
            const int choff = (((h << 2) | c0) ^ gx) * 8;   // halves
            uint4 av[4][2];
            #pragma unroll
            for (int mf = 0; mf < 4; mf++) {
                const __half* ap = As + (wm * 64 + mf * 16 + g) * BK + choff;
                av[mf][0] = *(const uint4*)ap;
                av[mf][1] = *(const uint4*)(ap + 8 * BK);
            }
            uint4 bv[4];
            #pragma unroll
            for (int nf = 0; nf < 4; nf++)
                bv[nf] = *(const uint4*)(Bs + (wn * 32 + nf * 8 + g) * BK + choff);

            #pragma unroll
            for (int mf = 0; mf < 4; mf++)
                #pragma unroll
                for (int nf = 0; nf < 4; nf++) {
                    mma_f16(acc[mf][nf], av[mf][0].x, av[mf][1].x, av[mf][0].y, av[mf][1].y,
                            bv[nf].x, bv[nf].y);
                    mma_f16(acc[mf][nf], av[mf][0].z, av[mf][1].z, av[mf][0].w, av[mf][1].w,
                            bv[nf].z, bv[nf].w);
                }
        }

        cs = ns;
        ns = (ns == NSTG - 1) ? 0 : ns + 1;
    }

    if (MODE == 0) {
        #pragma unroll
        for (int mf = 0; mf < 4; mf++) {
            int row0 = bm + wm * 64 + mf * 16 + g;
            #pragma unroll
            for (int nf = 0; nf < 4; nf++) {
                int coll = wn * 32 + nf * 8 + c0 * 2;
                float bx = sbias[coll], by = sbias[coll + 1];
                #pragma unroll
                for (int half_ = 0; half_ < 2; half_++) {
                    int row = row0 + half_ * 8;
                    if (row < M) {
                        float vx = fmaxf(acc[mf][nf][half_ * 2 + 0] + bx, 0.0f);
                        float vy = fmaxf(acc[mf][nf][half_ * 2 + 1] + by, 0.0f);
                        int cx = bn + coll;
                        int p = (cx & 31) >> 1;
                        int pp = ((p & 3) << 2) | (p >> 2);
                        __half2* dst = (__half2*)((__half*)Cout +
                                       (size_t)row * DIM_FC + (cx & ~31) + 2 * pp);
                        *dst = __floats2half2_rn(vx, vy);
                    }
                }
            }
        }
    } else {
        #pragma unroll
        for (int mf = 0; mf < 4; mf++) {
            #pragma unroll
            for (int half_ = 0; half_ < 2; half_++) {
                float p0 = 0.f, p1 = 0.f, p2 = 0.f;
                #pragma unroll
                for (int nf = 0; nf < 4; nf++) {
                    int coll = wn * 32 + nf * 8 + c0 * 2;
                    float vx = fmaxf(acc[mf][nf][half_ * 2 + 0] + sbias[coll], 0.0f);
                    float vy = fmaxf(acc[mf][nf][half_ * 2 + 1] + sbias[coll + 1], 0.0f);
                    p0 += vx * sW3[coll * 3 + 0] + vy * sW3[coll * 3 + 3];
                    p1 += vx * sW3[coll * 3 + 1] + vy * sW3[coll * 3 + 4];
                    p2 += vx * sW3[coll * 3 + 2] + vy * sW3[coll * 3 + 5];
                }
                p0 += __shfl_xor_sync(0xFFFFFFFFu, p0, 1);
                p1 += __shfl_xor_sync(0xFFFFFFFFu, p1, 1);
                p2 += __shfl_xor_sync(0xFFFFFFFFu, p2, 1);
                p0 += __shfl_xor_sync(0xFFFFFFFFu, p0, 2);
                p1 += __shfl_xor_sync(0xFFFFFFFFu, p1, 2);
                p2 += __shfl_xor_sync(0xFFFFFFFFu, p2, 2);
                if (c0 == 0) {
                    int lr = wm * 64 + mf * 16 + g + half_ * 8;
                    sP[wn][lr][0] = p0;
                    sP[wn][lr][1] = p1;
                    sP[wn][lr][2] = p2;
                }
            }
        }
        __syncthreads();
        float* part = (float*)Cout + (size_t)blockIdx.x * NLINES * NLAB;
        for (int i = tid; i < BM * NLAB; i += 256) {
            int lr = i / NLAB, lab = i % NLAB;
            int row = bm + lr;
            if (row < M)
                part[(size_t)row * NLAB + lab] =
                    sP[0][lr][lab] + sP[1][lr][lab] + sP[2][lr][lab] + sP[3][lr][lab];
        }
    }
}

// ---------------- kernel 5: reduce 8 partials + bias -> out ----------------
__global__ void reduce_out_kernel(const float* __restrict__ b3, float* __restrict__ out) {
    int i = blockIdx.x * 256 + threadIdx.x;
    if (i < NLINES * NLAB) {
        int lab = i % NLAB;
        float s = b3[lab];
        #pragma unroll
        for (int p = 0; p < 8; p++) s += g_part[p * NLINES * NLAB + i];
        out[i] = s;
    }
}

// ---------------- launch ---------------------------------------------------
extern "C" void kernel_launch(void* const* d_in, const int* in_sizes, int n_in,
                              void* d_out, int out_size) {
    const float* jloc = (const float*)d_in[0];
    const float* joff = (const float*)d_in[1];
    const float* loi  = (const float*)d_in[2];
    const int*   edge = (const int*)d_in[3];
    const float* W1   = (const float*)d_in[4];
    const float* b1   = (const float*)d_in[5];
    const float* W2   = (const float*)d_in[6];
    const float* b2   = (const float*)d_in[7];
    const float* W3   = (const float*)d_in[8];
    const float* b3   = (const float*)d_in[9];
    float* out = (float*)d_out;

    const int GEMM_SMEM = NSTG * STAGE * sizeof(__half);   // 98304 B
    cudaFuncSetAttribute(hgemm_kernel<0>,
                         cudaFuncAttributeMaxDynamicSharedMemorySize, GEMM_SMEM);
    cudaFuncSetAttribute(hgemm_kernel<1>,
                         cudaFuncAttributeMaxDynamicSharedMemorySize, GEMM_SMEM);

    __half *feats, *h1, *w1T, *w2T;
    float *part;
    cudaGetSymbolAddress((void**)&feats, g_feats);
    cudaGetSymbolAddress((void**)&h1, g_h1);
    cudaGetSymbolAddress((void**)&w1T, g_w1T);
    cudaGetSymbolAddress((void**)&w2T, g_w2T);
    cudaGetSymbolAddress((void**)&part, g_part);

    // side stream + events, created once on the (uncaptured) correctness call
    static cudaStream_t s1 = nullptr;
    static cudaEvent_t e0 = nullptr, e1 = nullptr, e2 = nullptr, e4 = nullptr;
    if (!s1) {
        cudaStreamCreateWithFlags(&s1, cudaStreamNonBlocking);
        cudaEventCreateWithFlags(&e0, cudaEventDisableTiming);
        cudaEventCreateWithFlags(&e1, cudaEventDisableTiming);
        cudaEventCreateWithFlags(&e2, cudaEventDisableTiming);
        cudaEventCreateWithFlags(&e4, cudaEventDisableTiming);
    }

    const int M1 = M_SPLIT;            // rows [0, M1)  : 78 gemm blocks, 4992 sample blocks
    const int M2 = NLINES - M_SPLIT;   // rows [M1, NLINES): 79 gemm blocks

    // main: topk.  side: transposes (independent of topk)
    topk_juncs_kernel<<<1, 1024>>>(jloc, joff);
    cudaEventRecord(e0, 0);
    cudaStreamWaitEvent(s1, e0, 0);    // fork s1 into the capture
    transpose_loi_kernel<<<dim3(NPIX / 32, DIM_LOI / 32), dim3(32, 8), 0, s1>>>(loi);
    transposeW_kernel<<<dim3(32, 32, 2), dim3(32, 8), 0, s1>>>(W1, W2);
    cudaEventRecord(e1, s1);
    cudaStreamWaitEvent(0, e1, 0);     // main now has topk + loiTh + weights

    // sample half 1, then fork gemm0 half 1 while sampling half 2
    sample_kernel<<<M1 / 2, 256>>>(edge, 0);
    cudaEventRecord(e2, 0);
    cudaStreamWaitEvent(s1, e2, 0);
    hgemm_kernel<0><<<dim3(8, M1 / BM), 256, GEMM_SMEM, s1>>>(
        feats, w1T, b1, nullptr, h1, NLINES, 0);
    hgemm_kernel<1><<<dim3(8, M1 / BM), 256, GEMM_SMEM, s1>>>(
        h1, w2T, b2, W3, part, NLINES, 0);
    cudaEventRecord(e4, s1);

    sample_kernel<<<M2 / 2, 256>>>(edge, M1);
    hgemm_kernel<0><<<dim3(8, (M2 + BM - 1) / BM), 256, GEMM_SMEM>>>(
        feats, w1T, b1, nullptr, h1, NLINES, M1);
    hgemm_kernel<1><<<dim3(8, (M2 + BM - 1) / BM), 256, GEMM_SMEM>>>(
        h1, w2T, b2, W3, part, NLINES, M1);

    cudaStreamWaitEvent(0, e4, 0);     // join side stream before the final reduce
    reduce_out_kernel<<<(NLINES * NLAB + 255) / 256, 256>>>(b3, out);
}

// round 16
// speedup vs baseline: 1.0243x; 1.0243x over previous
#include <cuda_runtime.h>
#include <cuda_fp16.h>
#include <math.h>
#include <cstdint>

#define HW 128
#define NPIX (HW*HW)          // 16384
#define TOPK 300
#define NLINES 20000
#define DIM_LOI 128
#define NPTS0 32
#define NPTS1 8
#define DIM_FC 1024
#define NLAB 3

// pair-permutation within a 32-k block (16 pairs): p' = (p&3)*4 + (p>>2)
__host__ __device__ __forceinline__ int khperm(int k) {
    int p = k >> 1;
    int pp = ((p & 3) << 2) | (p >> 2);
    return (pp << 1) | (k & 1);
}

// ---------------- scratch (device globals; no allocation allowed) ----------
__device__ __align__(16) __half g_loiTh[NPIX * DIM_LOI];   // [hw][c] fp16 4 MB
__device__ __align__(16) float  g_juncs[TOPK * 2];
__device__ __align__(16) __half g_feats[NLINES * DIM_FC];  // permuted fp16
__device__ __align__(16) __half g_h1[NLINES * DIM_FC];     // permuted fp16
__device__ __align__(16) __half g_w1T[DIM_FC * DIM_FC];    // W1^T [N][kperm]
__device__ __align__(16) __half g_w2T[DIM_FC * DIM_FC];    // W2^T [N][kperm]
__device__ __align__(16) float  g_part[8 * NLINES * NLAB]; // fused-out partials

// ======================= PTX helpers ========================================
__device__ __forceinline__ uint32_t smem_u32(const void* p) {
    uint32_t a;
    asm("{ .reg .u64 t; cvta.to.shared.u64 t, %1; cvt.u32.u64 %0, t; }" : "=r"(a) : "l"(p));
    return a;
}
#define CP_ASYNC16(sm, g) \
    asm volatile("cp.async.cg.shared.global [%0], [%1], 16;" :: "r"(sm), "l"(g) : "memory")
#define CP_COMMIT() asm volatile("cp.async.commit_group;" ::: "memory")
#define CP_WAIT(n)  asm volatile("cp.async.wait_group %0;" :: "n"(n) : "memory")

__device__ __forceinline__ void mma_f16(float* c,
                                        uint32_t a0, uint32_t a1, uint32_t a2, uint32_t a3,
                                        uint32_t b0, uint32_t b1) {
    asm volatile(
        "mma.sync.aligned.m16n8k16.row.col.f32.f16.f16.f32 "
        "{%0,%1,%2,%3}, {%4,%5,%6,%7}, {%8,%9}, {%0,%1,%2,%3};"
        : "+f"(c[0]), "+f"(c[1]), "+f"(c[2]), "+f"(c[3])
        : "r"(a0), "r"(a1), "r"(a2), "r"(a3), "r"(b0), "r"(b1));
}

// ---------------- kernel 1: NMS + compact + small bitonic top-k ------------
#define SORTN 4096
__global__ void topk_juncs_kernel(const float* __restrict__ jloc,
                                  const float* __restrict__ joff) {
    __shared__ unsigned long long keys[SORTN];
    __shared__ int cnt;
    int tid = threadIdx.x;
    if (tid == 0) cnt = 0;
    #pragma unroll
    for (int i = tid; i < SORTN; i += 1024) keys[i] = 0ull;
    __syncthreads();

    for (int i = tid; i < NPIX; i += 1024) {
        int y = i >> 7, x = i & 127;
        float v = jloc[i];
        float m = v;
        #pragma unroll
        for (int dy = -1; dy <= 1; dy++)
            #pragma unroll
            for (int dx = -1; dx <= 1; dx++) {
                int yy = y + dy, xx = x + dx;
                if (yy >= 0 && yy < HW && xx >= 0 && xx < HW)
                    m = fmaxf(m, jloc[yy * HW + xx]);
            }
        if (v == m && v > 0.0f) {
            int p = atomicAdd(&cnt, 1);
            if (p < SORTN)
                keys[p] = ((unsigned long long)__float_as_uint(v) << 32)
                        | (unsigned long long)(0xFFFFFFFFu - (unsigned)i);
        }
    }
    __syncthreads();

    for (int k = 2; k <= SORTN; k <<= 1) {
        for (int j = k >> 1; j > 0; j >>= 1) {
            #pragma unroll
            for (int i = tid; i < SORTN; i += 1024) {
                int ixj = i ^ j;
                if (ixj > i) {
                    unsigned long long a = keys[i], b = keys[ixj];
                    bool up = ((i & k) == 0);
                    if ((a < b) == up) { keys[i] = b; keys[ixj] = a; }
                }
            }
            __syncthreads();
        }
    }

    if (tid < TOPK) {
        unsigned long long key = keys[tid];
        unsigned idx = 0xFFFFFFFFu - (unsigned)(key & 0xFFFFFFFFull);
        float j0 = joff[idx];
        float j1 = joff[NPIX + idx];
        float sx = 1.0f / (1.0f + expf(-j0));
        float sy = 1.0f / (1.0f + expf(-j1));
        g_juncs[2 * tid + 0] = (float)(idx & 127) + sx;
        g_juncs[2 * tid + 1] = (float)(idx >> 7) + sy;
    }
}

// ---------------- kernel 2a: transpose loi [C][HW*HW] -> [HW*HW][C] fp16 ---
__global__ void transpose_loi_kernel(const float* __restrict__ in) {
    __shared__ float tile[32][33];
    int p0 = blockIdx.x * 32;
    int c0 = blockIdx.y * 32;
    int tx = threadIdx.x, ty = threadIdx.y;   // 32 x 8
    #pragma unroll
    for (int i = 0; i < 32; i += 8)
        tile[ty + i][tx] = in[(size_t)(c0 + ty + i) * NPIX + p0 + tx];
    __syncthreads();
    #pragma unroll
    for (int i = 0; i < 32; i += 8)
        g_loiTh[(size_t)(p0 + ty + i) * DIM_LOI + c0 + tx] =
            __float2half_rn(tile[tx][ty + i]);
}

// ---------------- kernel 2b: both W -> W^T with k-perm + fp16 (z = which) --
__global__ void transposeW_kernel(const float* __restrict__ W1,
                                  const float* __restrict__ W2) {
    __shared__ float tile[32][33];
    const float* in = blockIdx.z ? W2 : W1;
    __half* out = blockIdx.z ? g_w2T : g_w1T;
    int p0 = blockIdx.x * 32;   // n block
    int c0 = blockIdx.y * 32;   // k block
    int tx = threadIdx.x, ty = threadIdx.y;   // 32 x 8
    #pragma unroll
    for (int i = 0; i < 32; i += 8)
        tile[ty + i][tx] = in[(size_t)(c0 + ty + i) * DIM_FC + p0 + tx];
    __syncthreads();
    #pragma unroll
    for (int i = 0; i < 32; i += 8)
        out[(size_t)(p0 + ty + i) * DIM_FC + c0 + khperm(tx)] =
            __float2half_rn(tile[tx][ty + i]);
}

// ---------------- kernel 3: line sampling + bilinear + group max -----------
// 256 threads, 2 lines per block.
__global__ void sample_kernel(const int* __restrict__ edge) {
    __shared__ int   s_off[2][NPTS0][4];
    __shared__ float s_w[2][NPTS0][4];
    __shared__ __align__(16) float s_out[2][8][136];

    int n0 = blockIdx.x * 2;
    int tid = threadIdx.x;
    int li  = tid >> 7;          // which line (0/1)
    int t128 = tid & 127;
    int pg = t128 >> 4;          // maxpool group 0..7
    int cq = t128 & 15;          // 8-channel chunk (16 B fp16)

    if (tid < 64) {
        int l = tid >> 5;        // line
        int pt = tid & 31;       // point
        int n = n0 + l;
        int e0 = edge[2 * n + 0];
        int e1 = edge[2 * n + 1];
        float Ux = g_juncs[2 * e0 + 0], Uy = g_juncs[2 * e0 + 1];
        float Vx = g_juncs[2 * e1 + 0], Vy = g_juncs[2 * e1 + 1];
        float t = (float)pt * (1.0f / 31.0f);
        float px = Ux * t + Vx * (1.0f - t) - 0.5f;
        float py = Uy * t + Vy * (1.0f - t) - 0.5f;
        float x0 = fminf(fmaxf(floorf(px), 0.0f), 127.0f);
        float y0 = fminf(fmaxf(floorf(py), 0.0f), 127.0f);
        float x1 = fminf(x0 + 1.0f, 127.0f);
        float y1 = fminf(y0 + 1.0f, 127.0f);
        int ix0 = (int)x0, iy0 = (int)y0, ix1 = (int)x1, iy1 = (int)y1;
        s_off[l][pt][0] = (iy0 * HW + ix0) * DIM_LOI;
        s_off[l][pt][1] = (iy1 * HW + ix0) * DIM_LOI;
        s_off[l][pt][2] = (iy0 * HW + ix1) * DIM_LOI;
        s_off[l][pt][3] = (iy1 * HW + ix1) * DIM_LOI;
        s_w[l][pt][0] = (y1 - py) * (x1 - px);
        s_w[l][pt][1] = (py - y0) * (x1 - px);
        s_w[l][pt][2] = (y1 - py) * (px - x0);
        s_w[l][pt][3] = (py - y0) * (px - x0);
    }
    __syncthreads();

    float m[8];
    #pragma unroll
    for (int i = 0; i < 8; i++) m[i] = -1e30f;

    #pragma unroll
    for (int k = 0; k < 4; k++) {
        int p = pg * 4 + k;
        float w0 = s_w[li][p][0], w1 = s_w[li][p][1];
        float w2 = s_w[li][p][2], w3 = s_w[li][p][3];
        uint4 u0 = *(const uint4*)(g_loiTh + s_off[li][p][0] + cq * 8);
        uint4 u1 = *(const uint4*)(g_loiTh + s_off[li][p][1] + cq * 8);
        uint4 u2 = *(const uint4*)(g_loiTh + s_off[li][p][2] + cq * 8);
        uint4 u3 = *(const uint4*)(g_loiTh + s_off[li][p][3] + cq * 8);
        const __half2* h0 = (const __half2*)&u0;
        const __half2* h1 = (const __half2*)&u1;
        const __half2* h2 = (const __half2*)&u2;
        const __half2* h3 = (const __half2*)&u3;
        #pragma unroll
        for (int j = 0; j < 4; j++) {
            float2 a = __half22float2(h0[j]);
            float2 b = __half22float2(h1[j]);
            float2 c = __half22float2(h2[j]);
            float2 d = __half22float2(h3[j]);
            float vx = w0 * a.x + w1 * b.x + w2 * c.x + w3 * d.x;
            float vy = w0 * a.y + w1 * b.y + w2 * c.y + w3 * d.y;
            m[2 * j + 0] = fmaxf(m[2 * j + 0], vx);
            m[2 * j + 1] = fmaxf(m[2 * j + 1], vy);
        }
    }

    // conflict-free staging: 16-lane group writes 256 contiguous bytes
    {
        float4* dst = (float4*)&s_out[li][pg][cq * 8];
        dst[0] = make_float4(m[0], m[1], m[2], m[3]);
        dst[1] = make_float4(m[4], m[5], m[6], m[7]);
    }
    __syncthreads();

    // emit permuted fp16 feats: feature f = ch*8 + pg  ->  s_out[li][f&7][f>>3]
    {
        size_t base = (size_t)(n0 + li) * DIM_FC;
        #pragma unroll
        for (int r = 0; r < 8; r++) {
            int f = t128 + 128 * r;
            float v = s_out[li][f & 7][f >> 3];
            int pos = (f & ~31) | khperm(f & 31);
            g_feats[base + pos] = __float2half_rn(v);
        }
    }
}

// ---------------- kernel 4: fp16 mma GEMM, 128x128 tile, 64x32 warp tile ---
// BK=64, 3-stage cp.async ring, one __syncthreads per k-tile, XOR swizzle.
// MODE 0: C = relu(A@BT^T + bias), fp16 k-permuted out
// MODE 1: fused final: partial[bx][row][lab] = sum_cols relu(acc+bias)*W3[col][lab]
#define BK 64                          // halves per k-tile (128 B per row)
#define NKT (DIM_FC / BK)              // 16
#define BM 128
#define BN 128
#define ATILE (BM * BK)                // 8192 halves
#define BTILE (BN * BK)
#define STAGE (ATILE + BTILE)          // 16384 halves = 32 KB
#define NSTG 3

template <int MODE>
__global__ __launch_bounds__(256, 2)
void hgemm_kernel(const __half* __restrict__ A, const __half* __restrict__ BT,
                  const float* __restrict__ bias, const float* __restrict__ W3,
                  void* __restrict__ Cout, int M)
{
    extern __shared__ __half smem[];   // [NSTG][A | B]
    __shared__ float sbias[BN];
    __shared__ float sW3[BN * NLAB];
    __shared__ float sP[4][BM][NLAB];
    const uint32_t sbase = smem_u32(smem);
    const int tid = threadIdx.x;
    const int lane = tid & 31;
    const int warp = tid >> 5;
    const int wm = warp & 1;           // 2 row slabs of 64
    const int wn = warp >> 1;          // 4 col slabs of 32
    const int bn = blockIdx.x * BN;
    const int bm = blockIdx.y * BM;

    if (tid < BN) sbias[tid] = bias[bn + tid];
    if (MODE == 1) {
        #pragma unroll
        for (int i = tid; i < BN * NLAB; i += 256) sW3[i] = W3[bn * NLAB + i];
    }

    // global->smem: 128 B per row -> 8 threads/row (16 B chunks, xor-swizzled)
    const int lrow = tid >> 3;         // 0..31
    const int lchk = tid & 7;          // 16B chunk index
    const int schk = lchk ^ ((lrow & 1) << 2);   // swizzled chunk

    const __half* gA[4];
    uint32_t sA[4];
    const __half* gB[4];
    uint32_t sB[4];
    #pragma unroll
    for (int i = 0; i < 4; i++) {
        int row = lrow + 32 * i;       // parity(row) == parity(lrow)
        int ar = bm + row; if (ar >= M) ar = M - 1;
        gA[i] = A + (size_t)ar * DIM_FC + lchk * 8;
        sA[i] = sbase + (row * BK + schk * 8) * 2;
        gB[i] = BT + (size_t)(bn + row) * DIM_FC + lchk * 8;
        sB[i] = sbase + (ATILE + row * BK + schk * 8) * 2;
    }

    float acc[4][4][4];
    #pragma unroll
    for (int mf = 0; mf < 4; mf++)
        #pragma unroll
        for (int nf = 0; nf < 4; nf++)
            #pragma unroll
            for (int qq = 0; qq < 4; qq++) acc[mf][nf][qq] = 0.0f;

    // prologue: ktile 0 -> stage 0
    #pragma unroll
    for (int i = 0; i < 4; i++) {
        CP_ASYNC16(sA[i], gA[i]);
        CP_ASYNC16(sB[i], gB[i]);
    }
    CP_COMMIT();

    const int g  = lane >> 2;
    const int c0 = lane & 3;
    const int gx = (g & 1) << 2;       // frag chunk xor (row parity = g&1)

    int cs = 0;                        // current stage
    int ns = 1;                        // next stage
    for (int kt = 0; kt < NKT; kt++) {
        if (kt + 1 < NKT) {
            uint32_t soff = (uint32_t)ns * (STAGE * 2);
            int goff = (kt + 1) * BK;
            #pragma unroll
            for (int i = 0; i < 4; i++) {
                CP_ASYNC16(sA[i] + soff, gA[i] + goff);
                CP_ASYNC16(sB[i] + soff, gB[i] + goff);
            }
            CP_COMMIT();
            CP_WAIT(1);
        } else {
            CP_WAIT(0);
        }
        __syncthreads();

        const __half* As = smem + cs * STAGE;
        const __half* Bs = As + ATILE;

        #pragma unroll
        for (int h = 0; h < 2; h++) {  // two 32-k half-blocks
            const int choff = (((h << 2) | c0) ^ gx) * 8;   // halves
            uint4 av[4][2];
            #pragma unroll
            for (int mf = 0; mf < 4; mf++) {
                const __half* ap = As + (wm * 64 + mf * 16 + g) * BK + choff;
                av[mf][0] = *(const uint4*)ap;
                av[mf][1] = *(const uint4*)(ap + 8 * BK);
            }
            uint4 bv[4];
            #pragma unroll
            for (int nf = 0; nf < 4; nf++)
                bv[nf] = *(const uint4*)(Bs + (wn * 32 + nf * 8 + g) * BK + choff);

            #pragma unroll
            for (int mf = 0; mf < 4; mf++)
                #pragma unroll
                for (int nf = 0; nf < 4; nf++) {
                    mma_f16(acc[mf][nf], av[mf][0].x, av[mf][1].x, av[mf][0].y, av[mf][1].y,
                            bv[nf].x, bv[nf].y);
                    mma_f16(acc[mf][nf], av[mf][0].z, av[mf][1].z, av[mf][0].w, av[mf][1].w,
                            bv[nf].z, bv[nf].w);
                }
        }

        cs = ns;
        ns = (ns == NSTG - 1) ? 0 : ns + 1;
    }

    if (MODE == 0) {
        #pragma unroll
        for (int mf = 0; mf < 4; mf++) {
            int row0 = bm + wm * 64 + mf * 16 + g;
            #pragma unroll
            for (int nf = 0; nf < 4; nf++) {
                int coll = wn * 32 + nf * 8 + c0 * 2;
                float bx = sbias[coll], by = sbias[coll + 1];
                #pragma unroll
                for (int half_ = 0; half_ < 2; half_++) {
                    int row = row0 + half_ * 8;
                    if (row < M) {
                        float vx = fmaxf(acc[mf][nf][half_ * 2 + 0] + bx, 0.0f);
                        float vy = fmaxf(acc[mf][nf][half_ * 2 + 1] + by, 0.0f);
                        int cx = bn + coll;
                        int p = (cx & 31) >> 1;
                        int pp = ((p & 3) << 2) | (p >> 2);
                        __half2* dst = (__half2*)((__half*)Cout +
                                       (size_t)row * DIM_FC + (cx & ~31) + 2 * pp);
                        *dst = __floats2half2_rn(vx, vy);
                    }
                }
            }
        }
    } else {
        #pragma unroll
        for (int mf = 0; mf < 4; mf++) {
            #pragma unroll
            for (int half_ = 0; half_ < 2; half_++) {
                float p0 = 0.f, p1 = 0.f, p2 = 0.f;
                #pragma unroll
                for (int nf = 0; nf < 4; nf++) {
                    int coll = wn * 32 + nf * 8 + c0 * 2;
                    float vx = fmaxf(acc[mf][nf][half_ * 2 + 0] + sbias[coll], 0.0f);
                    float vy = fmaxf(acc[mf][nf][half_ * 2 + 1] + sbias[coll + 1], 0.0f);
                    p0 += vx * sW3[coll * 3 + 0] + vy * sW3[coll * 3 + 3];
                    p1 += vx * sW3[coll * 3 + 1] + vy * sW3[coll * 3 + 4];
                    p2 += vx * sW3[coll * 3 + 2] + vy * sW3[coll * 3 + 5];
                }
                p0 += __shfl_xor_sync(0xFFFFFFFFu, p0, 1);
                p1 += __shfl_xor_sync(0xFFFFFFFFu, p1, 1);
                p2 += __shfl_xor_sync(0xFFFFFFFFu, p2, 1);
                p0 += __shfl_xor_sync(0xFFFFFFFFu, p0, 2);
                p1 += __shfl_xor_sync(0xFFFFFFFFu, p1, 2);
                p2 += __shfl_xor_sync(0xFFFFFFFFu, p2, 2);
                if (c0 == 0) {
                    int lr = wm * 64 + mf * 16 + g + half_ * 8;
                    sP[wn][lr][0] = p0;
                    sP[wn][lr][1] = p1;
                    sP[wn][lr][2] = p2;
                }
            }
        }
        __syncthreads();
        float* part = (float*)Cout + (size_t)blockIdx.x * NLINES * NLAB;
        for (int i = tid; i < BM * NLAB; i += 256) {
            int lr = i / NLAB, lab = i % NLAB;
            int row = bm + lr;
            if (row < M)
                part[(size_t)row * NLAB + lab] =
                    sP[0][lr][lab] + sP[1][lr][lab] + sP[2][lr][lab] + sP[3][lr][lab];
        }
    }
}

// ---------------- kernel 5: reduce 8 partials + bias -> out ----------------
__global__ void reduce_out_kernel(const float* __restrict__ b3, float* __restrict__ out) {
    int i = blockIdx.x * 256 + threadIdx.x;
    if (i < NLINES * NLAB) {
        int lab = i % NLAB;
        float s = b3[lab];
        #pragma unroll
        for (int p = 0; p < 8; p++) s += g_part[p * NLINES * NLAB + i];
        out[i] = s;
    }
}

// ---------------- launch ---------------------------------------------------
extern "C" void kernel_launch(void* const* d_in, const int* in_sizes, int n_in,
                              void* d_out, int out_size) {
    const float* jloc = (const float*)d_in[0];
    const float* joff = (const float*)d_in[1];
    const float* loi  = (const float*)d_in[2];
    const int*   edge = (const int*)d_in[3];
    const float* W1   = (const float*)d_in[4];
    const float* b1   = (const float*)d_in[5];
    const float* W2   = (const float*)d_in[6];
    const float* b2   = (const float*)d_in[7];
    const float* W3   = (const float*)d_in[8];
    const float* b3   = (const float*)d_in[9];
    float* out = (float*)d_out;

    const int GEMM_SMEM = NSTG * STAGE * sizeof(__half);   // 98304 B
    cudaFuncSetAttribute(hgemm_kernel<0>,
                         cudaFuncAttributeMaxDynamicSharedMemorySize, GEMM_SMEM);
    cudaFuncSetAttribute(hgemm_kernel<1>,
                         cudaFuncAttributeMaxDynamicSharedMemorySize, GEMM_SMEM);

    __half *feats, *h1, *w1T, *w2T;
    float *part;
    cudaGetSymbolAddress((void**)&feats, g_feats);
    cudaGetSymbolAddress((void**)&h1, g_h1);
    cudaGetSymbolAddress((void**)&w1T, g_w1T);
    cudaGetSymbolAddress((void**)&w2T, g_w2T);
    cudaGetSymbolAddress((void**)&part, g_part);

    // side stream + events, created once on the (uncaptured) correctness call
    static cudaStream_t s1 = nullptr;
    static cudaEvent_t e0 = nullptr, e1 = nullptr;
    if (!s1) {
        cudaStreamCreateWithFlags(&s1, cudaStreamNonBlocking);
        cudaEventCreateWithFlags(&e0, cudaEventDisableTiming);
        cudaEventCreateWithFlags(&e1, cudaEventDisableTiming);
    }

    // fork FIRST: topk (1 block, main) runs concurrently with the transposes
    cudaEventRecord(e0, 0);
    cudaStreamWaitEvent(s1, e0, 0);
    transpose_loi_kernel<<<dim3(NPIX / 32, DIM_LOI / 32), dim3(32, 8), 0, s1>>>(loi);
    transposeW_kernel<<<dim3(32, 32, 2), dim3(32, 8), 0, s1>>>(W1, W2);
    cudaEventRecord(e1, s1);

    topk_juncs_kernel<<<1, 1024>>>(jloc, joff);

    cudaStreamWaitEvent(0, e1, 0);     // join: sample needs loiTh; gemms need wT

    sample_kernel<<<NLINES / 2, 256>>>(edge);

    dim3 ggrid(DIM_FC / BN, (NLINES + BM - 1) / BM);
    hgemm_kernel<0><<<ggrid, 256, GEMM_SMEM>>>(feats, w1T, b1, nullptr, h1, NLINES);
    hgemm_kernel<1><<<ggrid, 256, GEMM_SMEM>>>(h1, w2T, b2, W3, part, NLINES);

    reduce_out_kernel<<<(NLINES * NLAB + 255) / 256, 256>>>(b3, out);
}

// round 17
// speedup vs baseline: 1.0301x; 1.0056x over previous
#include <cuda_runtime.h>
#include <cuda_fp16.h>
#include <math.h>
#include <cstdint>

#define HW 128
#define NPIX (HW*HW)          // 16384
#define TOPK 300
#define NLINES 20000
#define DIM_LOI 128
#define NPTS0 32
#define NPTS1 8
#define DIM_FC 1024
#define NLAB 3

// pair-permutation within a 32-k block (16 pairs): p' = (p&3)*4 + (p>>2)
__host__ __device__ __forceinline__ int khperm(int k) {
    int p = k >> 1;
    int pp = ((p & 3) << 2) | (p >> 2);
    return (pp << 1) | (k & 1);
}

// ---------------- scratch (device globals; no allocation allowed) ----------
__device__ __align__(16) __half g_loiTh[NPIX * DIM_LOI];   // [hw][c] fp16 4 MB
__device__ __align__(16) float  g_juncs[TOPK * 2];
__device__ __align__(16) __half g_feats[NLINES * DIM_FC];  // permuted fp16
__device__ __align__(16) __half g_h1[NLINES * DIM_FC];     // permuted fp16
__device__ __align__(16) __half g_w1T[DIM_FC * DIM_FC];    // W1^T [N][kperm]
__device__ __align__(16) __half g_w2T[DIM_FC * DIM_FC];    // W2^T [N][kperm]
__device__ __align__(16) float  g_part[8 * NLINES * NLAB]; // fused-out partials

// ======================= PTX helpers ========================================
__device__ __forceinline__ uint32_t smem_u32(const void* p) {
    uint32_t a;
    asm("{ .reg .u64 t; cvta.to.shared.u64 t, %1; cvt.u32.u64 %0, t; }" : "=r"(a) : "l"(p));
    return a;
}
#define CP_ASYNC16(sm, g) \
    asm volatile("cp.async.cg.shared.global [%0], [%1], 16;" :: "r"(sm), "l"(g) : "memory")
#define CP_COMMIT() asm volatile("cp.async.commit_group;" ::: "memory")
#define CP_WAIT(n)  asm volatile("cp.async.wait_group %0;" :: "n"(n) : "memory")

__device__ __forceinline__ void mma_f16(float* c,
                                        uint32_t a0, uint32_t a1, uint32_t a2, uint32_t a3,
                                        uint32_t b0, uint32_t b1) {
    asm volatile(
        "mma.sync.aligned.m16n8k16.row.col.f32.f16.f16.f32 "
        "{%0,%1,%2,%3}, {%4,%5,%6,%7}, {%8,%9}, {%0,%1,%2,%3};"
        : "+f"(c[0]), "+f"(c[1]), "+f"(c[2]), "+f"(c[3])
        : "r"(a0), "r"(a1), "r"(a2), "r"(a3), "r"(b0), "r"(b1));
}

// ---------------- kernel 1: NMS + compact + small bitonic top-k ------------
#define SORTN 4096
__global__ void topk_juncs_kernel(const float* __restrict__ jloc,
                                  const float* __restrict__ joff) {
    __shared__ unsigned long long keys[SORTN];
    __shared__ int cnt;
    int tid = threadIdx.x;
    if (tid == 0) cnt = 0;
    #pragma unroll
    for (int i = tid; i < SORTN; i += 1024) keys[i] = 0ull;
    __syncthreads();

    for (int i = tid; i < NPIX; i += 1024) {
        int y = i >> 7, x = i & 127;
        float v = jloc[i];
        float m = v;
        #pragma unroll
        for (int dy = -1; dy <= 1; dy++)
            #pragma unroll
            for (int dx = -1; dx <= 1; dx++) {
                int yy = y + dy, xx = x + dx;
                if (yy >= 0 && yy < HW && xx >= 0 && xx < HW)
                    m = fmaxf(m, jloc[yy * HW + xx]);
            }
        if (v == m && v > 0.0f) {
            int p = atomicAdd(&cnt, 1);
            if (p < SORTN)
                keys[p] = ((unsigned long long)__float_as_uint(v) << 32)
                        | (unsigned long long)(0xFFFFFFFFu - (unsigned)i);
        }
    }
    __syncthreads();

    for (int k = 2; k <= SORTN; k <<= 1) {
        for (int j = k >> 1; j > 0; j >>= 1) {
            #pragma unroll
            for (int i = tid; i < SORTN; i += 1024) {
                int ixj = i ^ j;
                if (ixj > i) {
                    unsigned long long a = keys[i], b = keys[ixj];
                    bool up = ((i & k) == 0);
                    if ((a < b) == up) { keys[i] = b; keys[ixj] = a; }
                }
            }
            __syncthreads();
        }
    }

    if (tid < TOPK) {
        unsigned long long key = keys[tid];
        unsigned idx = 0xFFFFFFFFu - (unsigned)(key & 0xFFFFFFFFull);
        float j0 = joff[idx];
        float j1 = joff[NPIX + idx];
        float sx = 1.0f / (1.0f + expf(-j0));
        float sy = 1.0f / (1.0f + expf(-j1));
        g_juncs[2 * tid + 0] = (float)(idx & 127) + sx;
        g_juncs[2 * tid + 1] = (float)(idx >> 7) + sy;
    }
}

// ---------------- kernel 2a: transpose loi [C][HW*HW] -> [HW*HW][C] fp16 ---
__global__ void transpose_loi_kernel(const float* __restrict__ in) {
    __shared__ float tile[32][33];
    int p0 = blockIdx.x * 32;
    int c0 = blockIdx.y * 32;
    int tx = threadIdx.x, ty = threadIdx.y;   // 32 x 8
    #pragma unroll
    for (int i = 0; i < 32; i += 8)
        tile[ty + i][tx] = in[(size_t)(c0 + ty + i) * NPIX + p0 + tx];
    __syncthreads();
    #pragma unroll
    for (int i = 0; i < 32; i += 8)
        g_loiTh[(size_t)(p0 + ty + i) * DIM_LOI + c0 + tx] =
            __float2half_rn(tile[tx][ty + i]);
}

// ---------------- kernel 2b: both W -> W^T with k-perm + fp16 (z = which) --
__global__ void transposeW_kernel(const float* __restrict__ W1,
                                  const float* __restrict__ W2) {
    __shared__ float tile[32][33];
    const float* in = blockIdx.z ? W2 : W1;
    __half* out = blockIdx.z ? g_w2T : g_w1T;
    int p0 = blockIdx.x * 32;   // n block
    int c0 = blockIdx.y * 32;   // k block
    int tx = threadIdx.x, ty = threadIdx.y;   // 32 x 8
    #pragma unroll
    for (int i = 0; i < 32; i += 8)
        tile[ty + i][tx] = in[(size_t)(c0 + ty + i) * DIM_FC + p0 + tx];
    __syncthreads();
    #pragma unroll
    for (int i = 0; i < 32; i += 8)
        out[(size_t)(p0 + ty + i) * DIM_FC + c0 + khperm(tx)] =
            __float2half_rn(tile[tx][ty + i]);
}

// ---------------- kernel 3: line sampling + bilinear + group max -----------
// 256 threads, 2 lines per block. Corner tables packed as int4/float4 so each
// point costs 2 broadcast LDS.128 instead of 8 scalar LDS.
__global__ void sample_kernel(const int* __restrict__ edge) {
    __shared__ __align__(16) int4   s_off4[2][NPTS0];
    __shared__ __align__(16) float4 s_w4[2][NPTS0];
    __shared__ __align__(16) float  s_out[2][8][136];

    int n0 = blockIdx.x * 2;
    int tid = threadIdx.x;
    int li  = tid >> 7;          // which line (0/1)
    int t128 = tid & 127;
    int pg = t128 >> 4;          // maxpool group 0..7
    int cq = t128 & 15;          // 8-channel chunk (16 B fp16)

    if (tid < 64) {
        int l = tid >> 5;        // line
        int pt = tid & 31;       // point
        int n = n0 + l;
        int e0 = edge[2 * n + 0];
        int e1 = edge[2 * n + 1];
        float Ux = g_juncs[2 * e0 + 0], Uy = g_juncs[2 * e0 + 1];
        float Vx = g_juncs[2 * e1 + 0], Vy = g_juncs[2 * e1 + 1];
        float t = (float)pt * (1.0f / 31.0f);
        float px = Ux * t + Vx * (1.0f - t) - 0.5f;
        float py = Uy * t + Vy * (1.0f - t) - 0.5f;
        float x0 = fminf(fmaxf(floorf(px), 0.0f), 127.0f);
        float y0 = fminf(fmaxf(floorf(py), 0.0f), 127.0f);
        float x1 = fminf(x0 + 1.0f, 127.0f);
        float y1 = fminf(y0 + 1.0f, 127.0f);
        int ix0 = (int)x0, iy0 = (int)y0, ix1 = (int)x1, iy1 = (int)y1;
        s_off4[l][pt] = make_int4((iy0 * HW + ix0) * DIM_LOI,
                                  (iy1 * HW + ix0) * DIM_LOI,
                                  (iy0 * HW + ix1) * DIM_LOI,
                                  (iy1 * HW + ix1) * DIM_LOI);
        s_w4[l][pt] = make_float4((y1 - py) * (x1 - px),
                                  (py - y0) * (x1 - px),
                                  (y1 - py) * (px - x0),
                                  (py - y0) * (px - x0));
    }
    __syncthreads();

    float m[8];
    #pragma unroll
    for (int i = 0; i < 8; i++) m[i] = -1e30f;

    const __half* basep = g_loiTh + cq * 8;   // per-thread channel base

    #pragma unroll
    for (int k = 0; k < 4; k++) {
        int p = pg * 4 + k;
        int4   off = s_off4[li][p];
        float4 w   = s_w4[li][p];
        uint4 u0 = *(const uint4*)(basep + off.x);
        uint4 u1 = *(const uint4*)(basep + off.y);
        uint4 u2 = *(const uint4*)(basep + off.z);
        uint4 u3 = *(const uint4*)(basep + off.w);
        const __half2* h0 = (const __half2*)&u0;
        const __half2* h1 = (const __half2*)&u1;
        const __half2* h2 = (const __half2*)&u2;
        const __half2* h3 = (const __half2*)&u3;
        #pragma unroll
        for (int j = 0; j < 4; j++) {
            float2 a = __half22float2(h0[j]);
            float2 b = __half22float2(h1[j]);
            float2 c = __half22float2(h2[j]);
            float2 d = __half22float2(h3[j]);
            float vx = w.x * a.x + w.y * b.x + w.z * c.x + w.w * d.x;
            float vy = w.x * a.y + w.y * b.y + w.z * c.y + w.w * d.y;
            m[2 * j + 0] = fmaxf(m[2 * j + 0], vx);
            m[2 * j + 1] = fmaxf(m[2 * j + 1], vy);
        }
    }

    // conflict-free staging: 16-lane group writes 256 contiguous bytes
    {
        float4* dst = (float4*)&s_out[li][pg][cq * 8];
        dst[0] = make_float4(m[0], m[1], m[2], m[3]);
        dst[1] = make_float4(m[4], m[5], m[6], m[7]);
    }
    __syncthreads();

    // emit permuted fp16 feats: feature f = ch*8 + pg  ->  s_out[li][f&7][f>>3]
    {
        size_t base = (size_t)(n0 + li) * DIM_FC;
        #pragma unroll
        for (int r = 0; r < 8; r++) {
            int f = t128 + 128 * r;
            float v = s_out[li][f & 7][f >> 3];
            int pos = (f & ~31) | khperm(f & 31);
            g_feats[base + pos] = __float2half_rn(v);
        }
    }
}

// ---------------- kernel 4: fp16 mma GEMM, 128x128 tile, 64x32 warp tile ---
// BK=64, 3-stage cp.async ring, one __syncthreads per k-tile, XOR swizzle.
// MODE 0: C = relu(A@BT^T + bias), fp16 k-permuted out
// MODE 1: fused final: partial[bx][row][lab] = sum_cols relu(acc+bias)*W3[col][lab]
#define BK 64                          // halves per k-tile (128 B per row)
#define NKT (DIM_FC / BK)              // 16
#define BM 128
#define BN 128
#define ATILE (BM * BK)                // 8192 halves
#define BTILE (BN * BK)
#define STAGE (ATILE + BTILE)          // 16384 halves = 32 KB
#define NSTG 3

template <int MODE>
__global__ __launch_bounds__(256, 2)
void hgemm_kernel(const __half* __restrict__ A, const __half* __restrict__ BT,
                  const float* __restrict__ bias, const float* __restrict__ W3,
                  void* __restrict__ Cout, int M)
{
    extern __shared__ __half smem[];   // [NSTG][A | B]
    __shared__ float sbias[BN];
    __shared__ float sW3[BN * NLAB];
    __shared__ float sP[4][BM][NLAB];
    const uint32_t sbase = smem_u32(smem);
    const int tid = threadIdx.x;
    const int lane = tid & 31;
    const int warp = tid >> 5;
    const int wm = warp & 1;           // 2 row slabs of 64
    const int wn = warp >> 1;          // 4 col slabs of 32
    const int bn = blockIdx.x * BN;
    const int bm = blockIdx.y * BM;

    if (tid < BN) sbias[tid] = bias[bn + tid];
    if (MODE == 1) {
        #pragma unroll
        for (int i = tid; i < BN * NLAB; i += 256) sW3[i] = W3[bn * NLAB + i];
    }

    // global->smem: 128 B per row -> 8 threads/row (16 B chunks, xor-swizzled)
    const int lrow = tid >> 3;         // 0..31
    const int lchk = tid & 7;          // 16B chunk index
    const int schk = lchk ^ ((lrow & 1) << 2);   // swizzled chunk

    const __half* gA[4];
    uint32_t sA[4];
    const __half* gB[4];
    uint32_t sB[4];
    #pragma unroll
    for (int i = 0; i < 4; i++) {
        int row = lrow + 32 * i;       // parity(row) == parity(lrow)
        int ar = bm + row; if (ar >= M) ar = M - 1;
        gA[i] = A + (size_t)ar * DIM_FC + lchk * 8;
        sA[i] = sbase + (row * BK + schk * 8) * 2;
        gB[i] = BT + (size_t)(bn + row) * DIM_FC + lchk * 8;
        sB[i] = sbase + (ATILE + row * BK + schk * 8) * 2;
    }

    float acc[4][4][4];
    #pragma unroll
    for (int mf = 0; mf < 4; mf++)
        #pragma unroll
        for (int nf = 0; nf < 4; nf++)
            #pragma unroll
            for (int qq = 0; qq < 4; qq++) acc[mf][nf][qq] = 0.0f;

    // prologue: ktile 0 -> stage 0
    #pragma unroll
    for (int i = 0; i < 4; i++) {
        CP_ASYNC16(sA[i], gA[i]);
        CP_ASYNC16(sB[i], gB[i]);
    }
    CP_COMMIT();

    const int g  = lane >> 2;
    const int c0 = lane & 3;
    const int gx = (g & 1) << 2;       // frag chunk xor (row parity = g&1)

    int cs = 0;                        // current stage
    int ns = 1;                        // next stage
    for (int kt = 0; kt < NKT; kt++) {
        if (kt + 1 < NKT) {
            uint32_t soff = (uint32_t)ns * (STAGE * 2);
            int goff = (kt + 1) * BK;
            #pragma unroll
            for (int i = 0; i < 4; i++) {
                CP_ASYNC16(sA[i] + soff, gA[i] + goff);
                CP_ASYNC16(sB[i] + soff, gB[i] + goff);
            }
            CP_COMMIT();
            CP_WAIT(1);
        } else {
            CP_WAIT(0);
        }
        __syncthreads();

        const __half* As = smem + cs * STAGE;
        const __half* Bs = As + ATILE;

        #pragma unroll
        for (int h = 0; h < 2; h++) {  // two 32-k half-blocks
            const int choff = (((h << 2) | c0) ^ gx) * 8;   // halves
            uint4 av[4][2];
            #pragma unroll
            for (int mf = 0; mf < 4; mf++) {
                const __half* ap = As + (wm * 64 + mf * 16 + g) * BK + choff;
                av[mf][0] = *(const uint4*)ap;
                av[mf][1] = *(const uint4*)(ap + 8 * BK);
            }
            uint4 bv[4];
            #pragma unroll
            for (int nf = 0; nf < 4; nf++)
                bv[nf] = *(const uint4*)(Bs + (wn * 32 + nf * 8 + g) * BK + choff);

            #pragma unroll
            for (int mf = 0; mf < 4; mf++)
                #pragma unroll
                for (int nf = 0; nf < 4; nf++) {
                    mma_f16(acc[mf][nf], av[mf][0].x, av[mf][1].x, av[mf][0].y, av[mf][1].y,
                            bv[nf].x, bv[nf].y);
                    mma_f16(acc[mf][nf], av[mf][0].z, av[mf][1].z, av[mf][0].w, av[mf][1].w,
                            bv[nf].z, bv[nf].w);
                }
        }

        cs = ns;
        ns = (ns == NSTG - 1) ? 0 : ns + 1;
    }

    if (MODE == 0) {
        #pragma unroll
        for (int mf = 0; mf < 4; mf++) {
            int row0 = bm + wm * 64 + mf * 16 + g;
            #pragma unroll
            for (int nf = 0; nf < 4; nf++) {
                int coll = wn * 32 + nf * 8 + c0 * 2;
                float bx = sbias[coll], by = sbias[coll + 1];
                #pragma unroll
                for (int half_ = 0; half_ < 2; half_++) {
                    int row = row0 + half_ * 8;
                    if (row < M) {
                        float vx = fmaxf(acc[mf][nf][half_ * 2 + 0] + bx, 0.0f);
                        float vy = fmaxf(acc[mf][nf][half_ * 2 + 1] + by, 0.0f);
                        int cx = bn + coll;
                        int p = (cx & 31) >> 1;
                        int pp = ((p & 3) << 2) | (p >> 2);
                        __half2* dst = (__half2*)((__half*)Cout +
                                       (size_t)row * DIM_FC + (cx & ~31) + 2 * pp);
                        *dst = __floats2half2_rn(vx, vy);
                    }
                }
            }
        }
    } else {
        #pragma unroll
        for (int mf = 0; mf < 4; mf++) {
            #pragma unroll
            for (int half_ = 0; half_ < 2; half_++) {
                float p0 = 0.f, p1 = 0.f, p2 = 0.f;
                #pragma unroll
                for (int nf = 0; nf < 4; nf++) {
                    int coll = wn * 32 + nf * 8 + c0 * 2;
                    float vx = fmaxf(acc[mf][nf][half_ * 2 + 0] + sbias[coll], 0.0f);
                    float vy = fmaxf(acc[mf][nf][half_ * 2 + 1] + sbias[coll + 1], 0.0f);
                    p0 += vx * sW3[coll * 3 + 0] + vy * sW3[coll * 3 + 3];
                    p1 += vx * sW3[coll * 3 + 1] + vy * sW3[coll * 3 + 4];
                    p2 += vx * sW3[coll * 3 + 2] + vy * sW3[coll * 3 + 5];
                }
                p0 += __shfl_xor_sync(0xFFFFFFFFu, p0, 1);
                p1 += __shfl_xor_sync(0xFFFFFFFFu, p1, 1);
                p2 += __shfl_xor_sync(0xFFFFFFFFu, p2, 1);
                p0 += __shfl_xor_sync(0xFFFFFFFFu, p0, 2);
                p1 += __shfl_xor_sync(0xFFFFFFFFu, p1, 2);
                p2 += __shfl_xor_sync(0xFFFFFFFFu, p2, 2);
                if (c0 == 0) {
                    int lr = wm * 64 + mf * 16 + g + half_ * 8;
                    sP[wn][lr][0] = p0;
                    sP[wn][lr][1] = p1;
                    sP[wn][lr][2] = p2;
                }
            }
        }
        __syncthreads();
        float* part = (float*)Cout + (size_t)blockIdx.x * NLINES * NLAB;
        for (int i = tid; i < BM * NLAB; i += 256) {
            int lr = i / NLAB, lab = i % NLAB;
            int row = bm + lr;
            if (row < M)
                part[(size_t)row * NLAB + lab] =
                    sP[0][lr][lab] + sP[1][lr][lab] + sP[2][lr][lab] + sP[3][lr][lab];
        }
    }
}

// ---------------- kernel 5: reduce 8 partials + bias -> out ----------------
__global__ void reduce_out_kernel(const float* __restrict__ b3, float* __restrict__ out) {
    int i = blockIdx.x * 256 + threadIdx.x;
    if (i < NLINES * NLAB) {
        int lab = i % NLAB;
        float s = b3[lab];
        #pragma unroll
        for (int p = 0; p < 8; p++) s += g_part[p * NLINES * NLAB + i];
        out[i] = s;
    }
}

// ---------------- launch ---------------------------------------------------
extern "C" void kernel_launch(void* const* d_in, const int* in_sizes, int n_in,
                              void* d_out, int out_size) {
    const float* jloc = (const float*)d_in[0];
    const float* joff = (const float*)d_in[1];
    const float* loi  = (const float*)d_in[2];
    const int*   edge = (const int*)d_in[3];
    const float* W1   = (const float*)d_in[4];
    const float* b1   = (const float*)d_in[5];
    const float* W2   = (const float*)d_in[6];
    const float* b2   = (const float*)d_in[7];
    const float* W3   = (const float*)d_in[8];
    const float* b3   = (const float*)d_in[9];
    float* out = (float*)d_out;

    const int GEMM_SMEM = NSTG * STAGE * sizeof(__half);   // 98304 B
    cudaFuncSetAttribute(hgemm_kernel<0>,
                         cudaFuncAttributeMaxDynamicSharedMemorySize, GEMM_SMEM);
    cudaFuncSetAttribute(hgemm_kernel<1>,
                         cudaFuncAttributeMaxDynamicSharedMemorySize, GEMM_SMEM);

    __half *feats, *h1, *w1T, *w2T;
    float *part;
    cudaGetSymbolAddress((void**)&feats, g_feats);
    cudaGetSymbolAddress((void**)&h1, g_h1);
    cudaGetSymbolAddress((void**)&w1T, g_w1T);
    cudaGetSymbolAddress((void**)&w2T, g_w2T);
    cudaGetSymbolAddress((void**)&part, g_part);

    // side stream + events, created once on the (uncaptured) correctness call
    static cudaStream_t s1 = nullptr;
    static cudaEvent_t e0 = nullptr, e1 = nullptr;
    if (!s1) {
        cudaStreamCreateWithFlags(&s1, cudaStreamNonBlocking);
        cudaEventCreateWithFlags(&e0, cudaEventDisableTiming);
        cudaEventCreateWithFlags(&e1, cudaEventDisableTiming);
    }

    // fork FIRST: topk (1 block, main) runs concurrently with the transposes
    cudaEventRecord(e0, 0);
    cudaStreamWaitEvent(s1, e0, 0);
    transpose_loi_kernel<<<dim3(NPIX / 32, DIM_LOI / 32), dim3(32, 8), 0, s1>>>(loi);
    transposeW_kernel<<<dim3(32, 32, 2), dim3(32, 8), 0, s1>>>(W1, W2);
    cudaEventRecord(e1, s1);

    topk_juncs_kernel<<<1, 1024>>>(jloc, joff);

    cudaStreamWaitEvent(0, e1, 0);     // join: sample needs loiTh; gemms need wT

    sample_kernel<<<NLINES / 2, 256>>>(edge);

    dim3 ggrid(DIM_FC / BN, (NLINES + BM - 1) / BM);
    hgemm_kernel<0><<<ggrid, 256, GEMM_SMEM>>>(feats, w1T, b1, nullptr, h1, NLINES);
    hgemm_kernel<1><<<ggrid, 256, GEMM_SMEM>>>(h1, w2T, b2, W3, part, NLINES);

    reduce_out_kernel<<<(NLINES * NLAB + 255) / 256, 256>>>(b3, out);
}